// round 15
// baseline (speedup 1.0000x reference)
#include <cuda_runtime.h>
#include <cuda_bf16.h>
#include <cstdint>

// SudokuDigitsDoubles — exact boolean reduction ("naked pairs" row elimination).
//
// Round 15: split into two unidirectional kernels to beat the ~5.1 TB/s
// mixed read+write HBM floor every single-kernel variant converged to.
//   K1 (read-bound):  bulk-load tiles, 72 row leaders compute keep masks for
//                     ALL rows, store u32 masks to device scratch (10.6MB).
//   K2 (write-bound): read masks (L2-resident) and expand to coalesced float
//                     stores. Pure-write stream.

static constexpr int PUZ = 729;                  // floats per puzzle
static constexpr int PPB = 8;                    // puzzles per tile
static constexpr int NF  = PPB * PUZ;            // 5832 floats per tile
static constexpr unsigned TILE_BYTES = NF * 4;   // 23328
static constexpr int THREADS1 = 128;
static constexpr int GRID_CTAS = 592;            // 4 per SM * 148 SMs
static constexpr int MAX_PUZ = 65536;

// keep-mask scratch (static device global; not an allocation)
__device__ unsigned g_keep[(size_t)MAX_PUZ * 81];

__device__ __forceinline__ unsigned smem_u32(const void* p) {
    unsigned a;
    asm("{ .reg .u64 t; cvta.to.shared.u64 t, %1; cvt.u32.u64 %0, t; }"
        : "=r"(a) : "l"(p));
    return a;
}

__device__ __forceinline__ void mbar_wait(unsigned bar, unsigned parity) {
    unsigned done;
    do {
        asm volatile(
            "{\n\t.reg .pred p;\n\t"
            "mbarrier.try_wait.parity.acquire.cta.shared::cta.b64 p, [%1], %2;\n\t"
            "selp.b32 %0, 1, 0, p;\n\t}"
            : "=r"(done) : "r"(bar), "r"(parity) : "memory");
    } while (!done);
}

__device__ __forceinline__ void bulk_load(unsigned dst, const float* src,
                                          unsigned bar) {
    asm volatile("mbarrier.arrive.expect_tx.shared.b64 _, [%0], %1;"
                 :: "r"(bar), "r"(TILE_BYTES) : "memory");
    asm volatile(
        "cp.async.bulk.shared::cluster.global.mbarrier::complete_tx::bytes "
        "[%0], [%1], %2, [%3];"
        :: "r"(dst), "l"(src), "r"(TILE_BYTES), "r"(bar) : "memory");
}

// per-row naked-pair logic -> keep masks for all 9 cells
__device__ __forceinline__ void row_keep(const int m[9], int keep[9]) {
    int pv[9];
    #pragma unroll
    for (int c = 0; c < 9; c++)
        pv[c] = (__popc((unsigned)m[c]) == 2) ? m[c] : 0;
    int act = 0, tor = 0;
    #pragma unroll
    for (int j = 0; j < 9; j++) {
        int cc = 0;
        #pragma unroll
        for (int k = 0; k < 9; k++)
            cc += (pv[k] == pv[j]) ? 1 : 0;
        const bool a = (pv[j] != 0) & (cc == 2);
        act |= a ? (1 << j) : 0;
        tor |= a ? pv[j] : 0;
    }
    #pragma unroll
    for (int c = 0; c < 9; c++) {
        int erase;
        if ((act >> c) & 1) {
            erase = 0;
            #pragma unroll
            for (int j = 0; j < 9; j++)
                if (((act >> j) & 1) && pv[j] != pv[c])
                    erase |= pv[j];
        } else {
            erase = tor;
        }
        keep[c] = m[c] & ~erase;
    }
}

// ---- Kernel 1: read input tiles, compute keep masks (read-bound) ----
__global__ __launch_bounds__(THREADS1, 4)
void k1_masks(const float* __restrict__ in, int nPuz, int nTiles)
{
    __shared__ alignas(128) float buf[2][NF];
    __shared__ alignas(8) unsigned long long mbar[2];

    const unsigned tid = threadIdx.x;
    const unsigned sBar[2] = { smem_u32(&mbar[0]), smem_u32(&mbar[1]) };
    const unsigned sBuf[2] = { smem_u32(buf[0]),   smem_u32(buf[1])   };

    if (tid == 0) {
        asm volatile("mbarrier.init.shared.b64 [%0], 1;" :: "r"(sBar[0]) : "memory");
        asm volatile("mbarrier.init.shared.b64 [%0], 1;" :: "r"(sBar[1]) : "memory");
    }
    __syncthreads();

    int ph[2] = {0, 0};
    int b = 0;

    // prologue: first tile's load
    {
        const int tile = blockIdx.x;
        if (tid == 0 && tile < nTiles) {
            const int tb = tile * PPB;
            if (tb + PPB <= nPuz)
                bulk_load(sBuf[0], in + (size_t)tb * PUZ, sBar[0]);
        }
    }

    for (int tile = blockIdx.x; tile < nTiles; tile += gridDim.x, b ^= 1) {
        const int tileBase = tile * PPB;
        const bool full = (tileBase + PPB <= nPuz);

        // prefetch next tile (its buffer's compute finished last iteration)
        const int nextTile = tile + gridDim.x;
        if (tid == 0 && nextTile < nTiles) {
            const int ntb = nextTile * PPB;
            if (ntb + PPB <= nPuz)
                bulk_load(sBuf[b ^ 1], in + (size_t)ntb * PUZ, sBar[b ^ 1]);
        }

        if (full) {
            mbar_wait(sBar[b], (unsigned)ph[b]);
            ph[b] ^= 1;

            if (tid < PPB * 9) {
                const int pl = tid / 9;
                const int r  = tid - 9 * pl;
                const unsigned* rowp =
                    reinterpret_cast<const unsigned*>(buf[b]) + pl * PUZ + r * 9;
                int m[9], keep[9];
                #pragma unroll
                for (int c = 0; c < 9; c++) {
                    unsigned mm = 0;
                    #pragma unroll
                    for (int d = 0; d < 9; d++)
                        mm |= ((rowp[d * 81 + c] >> 23) & 1u) << d;  // 1.0f vs 0.0f
                    m[c] = (int)mm;
                }
                row_keep(m, keep);
                unsigned* kp = g_keep + (size_t)(tileBase + pl) * 81 + r * 9;
                #pragma unroll
                for (int c = 0; c < 9; c++)
                    kp[c] = (unsigned)keep[c];
            }
        } else {
            // partial tail tile: direct scalar path
            const int puzCount = nPuz - tileBase;
            if (puzCount > 0 && tid < (unsigned)(puzCount * 9)) {
                const int pl = tid / 9;
                const int r  = tid - 9 * pl;
                const float* gi = in + (size_t)(tileBase + pl) * PUZ + r * 9;
                int m[9], keep[9];
                #pragma unroll
                for (int c = 0; c < 9; c++) {
                    unsigned mm = 0;
                    #pragma unroll
                    for (int d = 0; d < 9; d++)
                        mm |= ((__float_as_uint(gi[d * 81 + c]) >> 23) & 1u) << d;
                    m[c] = (int)mm;
                }
                row_keep(m, keep);
                unsigned* kp = g_keep + (size_t)(tileBase + pl) * 81 + r * 9;
                #pragma unroll
                for (int c = 0; c < 9; c++)
                    kp[c] = (unsigned)keep[c];
            }
        }
        // compute on buffer b done before its reuse two iterations from now
        __syncthreads();
    }
}

// ---- Kernel 2: expand keep masks to output floats (write-bound) ----
static constexpr int THREADS2 = 256;

__global__ __launch_bounds__(THREADS2, 8)
void k2_expand(float* __restrict__ out, int nPuz)
{
    const int basePuz = blockIdx.x * PPB;
    const int puzCount = min(PPB, nPuz - basePuz);
    const int nActive = puzCount * 81;

    #pragma unroll
    for (int it = 0; it < 3; ++it) {
        const int j = threadIdx.x + it * THREADS2;
        if (j < nActive) {
            const int pl = j / 81;
            const int rc = j - pl * 81;
            const unsigned keep = g_keep[(size_t)(basePuz + pl) * 81 + rc];
            float* p = out + (size_t)(basePuz + pl) * PUZ + rc;
            #pragma unroll
            for (int d = 0; d < 9; d++)
                p[d * 81] = ((keep >> d) & 1) ? 1.0f : 0.0f;
        }
    }
}

// ---- fallback for nPuz > MAX_PUZ (not hit for this dataset): fused scalar ----
__global__ __launch_bounds__(256, 8)
void k_fallback(const float* __restrict__ in, float* __restrict__ out, int nPuz)
{
    const int t = blockIdx.x * blockDim.x + threadIdx.x;  // one thread per row
    if (t >= nPuz * 9) return;
    const int puz = t / 9;
    const int r   = t - 9 * puz;
    const float* gi = in  + (size_t)puz * PUZ + r * 9;
    float*       go = out + (size_t)puz * PUZ + r * 9;
    int m[9], keep[9];
    #pragma unroll
    for (int c = 0; c < 9; c++) {
        unsigned mm = 0;
        #pragma unroll
        for (int d = 0; d < 9; d++)
            mm |= ((__float_as_uint(gi[d * 81 + c]) >> 23) & 1u) << d;
        m[c] = (int)mm;
    }
    row_keep(m, keep);
    #pragma unroll
    for (int c = 0; c < 9; c++)
        #pragma unroll
        for (int d = 0; d < 9; d++)
            go[d * 81 + c] = ((keep[c] >> d) & 1) ? 1.0f : 0.0f;
}

extern "C" void kernel_launch(void* const* d_in, const int* in_sizes, int n_in,
                              void* d_out, int out_size)
{
    const float* mask = (const float*)d_in[0];
    float* out = (float*)d_out;
    const int nPuz = in_sizes[0] / PUZ;                 // 32768

    if (nPuz > MAX_PUZ) {
        const int nRows = nPuz * 9;
        k_fallback<<<(nRows + 255) / 256, 256>>>(mask, out, nPuz);
        return;
    }

    const int nTiles = (nPuz + PPB - 1) / PPB;          // 4096
    const int grid1 = (nTiles < GRID_CTAS) ? nTiles : GRID_CTAS;
    k1_masks<<<grid1, THREADS1>>>(mask, nPuz, nTiles);
    k2_expand<<<nTiles, THREADS2>>>(out, nPuz);
}

// round 16
// speedup vs baseline: 1.3267x; 1.3267x over previous
#include <cuda_runtime.h>
#include <cuda_bf16.h>
#include <cstdint>

// SudokuDigitsDoubles — exact boolean reduction ("naked pairs" row elimination).
//
// Round 16: R14 (persistent CTAs, double-buffered cp.async.bulk in/out, L2
// hints, 4 CTAs/SM, grid 592) with THREADS=96: the steady-state work set is
// tid0 (bulk ops) + tids 0..71 (row leaders), so warp 3 of the 128-thread
// version only widened every barrier and mbarrier spin. 3 warps, all useful.
//
// 15 rounds of evidence: every structure converges to 191MB / ~5.1 TB/s
// mixed read+write HBM bandwidth; this config is the one that reaches that
// floor with minimal instruction overhead.

static constexpr int PUZ = 729;                  // floats per puzzle
static constexpr int PPB = 8;                    // puzzles per tile
static constexpr int NF  = PPB * PUZ;            // 5832 floats per tile
static constexpr unsigned TILE_BYTES = NF * 4;   // 23328
static constexpr int THREADS = 96;               // 3 warps, 72 leaders + tid0
static constexpr int GRID_CTAS = 592;            // 4 per SM * 148 SMs

__device__ __forceinline__ unsigned smem_u32(const void* p) {
    unsigned a;
    asm("{ .reg .u64 t; cvta.to.shared.u64 t, %1; cvt.u32.u64 %0, t; }"
        : "=r"(a) : "l"(p));
    return a;
}

__device__ __forceinline__ void mbar_wait(unsigned bar, unsigned parity) {
    unsigned done;
    do {
        asm volatile(
            "{\n\t.reg .pred p;\n\t"
            "mbarrier.try_wait.parity.acquire.cta.shared::cta.b64 p, [%1], %2;\n\t"
            "selp.b32 %0, 1, 0, p;\n\t}"
            : "=r"(done) : "r"(bar), "r"(parity) : "memory");
    } while (!done);
}

__device__ __forceinline__ void bulk_load_resident(unsigned dst, const float* src,
                                                   unsigned bar,
                                                   unsigned long long pol) {
    asm volatile("mbarrier.arrive.expect_tx.shared.b64 _, [%0], %1;"
                 :: "r"(bar), "r"(TILE_BYTES) : "memory");
    asm volatile(
        "cp.async.bulk.shared::cluster.global.mbarrier::complete_tx::bytes"
        ".L2::cache_hint [%0], [%1], %2, [%3], %4;"
        :: "r"(dst), "l"(src), "r"(TILE_BYTES), "r"(bar), "l"(pol) : "memory");
}

__global__ __launch_bounds__(THREADS, 4)
void sudoku_doubles_kernel(const float* __restrict__ in,
                           float* __restrict__ out,
                           int nPuz, int nTiles)
{
    __shared__ alignas(128) float buf[2][NF];
    __shared__ alignas(8) unsigned long long mbar[2];

    const unsigned tid = threadIdx.x;
    const unsigned sBar[2] = { smem_u32(&mbar[0]), smem_u32(&mbar[1]) };
    const unsigned sBuf[2] = { smem_u32(buf[0]),   smem_u32(buf[1])   };

    unsigned long long polLast, polFirst;
    asm("createpolicy.fractional.L2::evict_last.b64 %0, 1.0;"  : "=l"(polLast));
    asm("createpolicy.fractional.L2::evict_first.b64 %0, 1.0;" : "=l"(polFirst));

    if (tid == 0) {
        asm volatile("mbarrier.init.shared.b64 [%0], 1;" :: "r"(sBar[0]) : "memory");
        asm volatile("mbarrier.init.shared.b64 [%0], 1;" :: "r"(sBar[1]) : "memory");
    }
    __syncthreads();

    int ph[2] = {0, 0};
    int b = 0;

    // prologue: first tile's load
    {
        const int tile = blockIdx.x;
        if (tid == 0 && tile < nTiles) {
            const int tb = tile * PPB;
            if (tb + PPB <= nPuz)
                bulk_load_resident(sBuf[0], in + (size_t)tb * PUZ, sBar[0], polLast);
        }
    }

    for (int tile = blockIdx.x; tile < nTiles; tile += gridDim.x, b ^= 1) {
        const int tileBase = tile * PPB;
        const bool full = (tileBase + PPB <= nPuz);

        // ---- prefetch next tile into the other buffer ----
        const int nextTile = tile + gridDim.x;
        if (tid == 0 && nextTile < nTiles) {
            const int ntb = nextTile * PPB;
            if (ntb + PPB <= nPuz) {
                asm volatile("cp.async.bulk.wait_group.read 0;" ::: "memory");
                bulk_load_resident(sBuf[b ^ 1], in + (size_t)ntb * PUZ,
                                   sBar[b ^ 1], polLast);
            }
        }

        if (full) {
            mbar_wait(sBar[b], (unsigned)ph[b]);
            ph[b] ^= 1;

            // ---- 72 row leaders: logic directly on the smem tile ----
            if (tid < PPB * 9) {
                const int pl = tid / 9;
                const int r  = tid - 9 * pl;
                const unsigned* rowp =
                    reinterpret_cast<const unsigned*>(buf[b]) + pl * PUZ + r * 9;

                int m[9], pv[9];
                #pragma unroll
                for (int c = 0; c < 9; c++) {
                    unsigned mm = 0;
                    #pragma unroll
                    for (int d = 0; d < 9; d++)
                        mm |= ((rowp[d * 81 + c] >> 23) & 1u) << d;  // 1.0f vs 0.0f
                    m[c]  = (int)mm;
                    pv[c] = (__popc(mm) == 2) ? m[c] : 0;
                }
                int act = 0, tor = 0;
                #pragma unroll
                for (int j = 0; j < 9; j++) {
                    int cc = 0;
                    #pragma unroll
                    for (int k = 0; k < 9; k++)
                        cc += (pv[k] == pv[j]) ? 1 : 0;
                    const bool a = (pv[j] != 0) & (cc == 2);
                    act |= a ? (1 << j) : 0;
                    tor |= a ? pv[j] : 0;
                }
                if (act) {   // rare: ~0.5% of rows
                    float* o = buf[b] + pl * PUZ + r * 9;
                    #pragma unroll
                    for (int c = 0; c < 9; c++) {
                        int erase;
                        if ((act >> c) & 1) {
                            erase = 0;
                            #pragma unroll
                            for (int j = 0; j < 9; j++)
                                if (((act >> j) & 1) && pv[j] != pv[c])
                                    erase |= pv[j];
                        } else {
                            erase = tor;
                        }
                        const int keep = m[c] & ~erase;
                        #pragma unroll
                        for (int d = 0; d < 9; d++)
                            o[d * 81 + c] = ((keep >> d) & 1) ? 1.0f : 0.0f;
                    }
                }
            }
            __syncthreads();

            // ---- bulk store this tile (streaming, evict_first) ----
            if (tid == 0) {
                asm volatile("fence.proxy.async.shared::cta;" ::: "memory");
                asm volatile(
                    "cp.async.bulk.global.shared::cta.bulk_group"
                    ".L2::cache_hint [%0], [%1], %2, %3;"
                    :: "l"(out + (size_t)tileBase * PUZ), "r"(sBuf[b]),
                       "r"(TILE_BYTES), "l"(polFirst) : "memory");
                asm volatile("cp.async.bulk.commit_group;" ::: "memory");
            }
        } else {
            // ---- partial tail tile: direct scalar path (unused for B=32768) ----
            const int puzCount = nPuz - tileBase;
            if (puzCount > 0 && tid < (unsigned)(puzCount * 9)) {
                const int pl = tid / 9;
                const int r  = tid - 9 * pl;
                const float* gi = in  + (size_t)(tileBase + pl) * PUZ + r * 9;
                float*       go = out + (size_t)(tileBase + pl) * PUZ + r * 9;
                int m[9], pv[9];
                #pragma unroll
                for (int c = 0; c < 9; c++) {
                    unsigned mm = 0;
                    #pragma unroll
                    for (int d = 0; d < 9; d++)
                        mm |= ((__float_as_uint(gi[d * 81 + c]) >> 23) & 1u) << d;
                    m[c]  = (int)mm;
                    pv[c] = (__popc(mm) == 2) ? m[c] : 0;
                }
                int act = 0, tor = 0;
                #pragma unroll
                for (int j = 0; j < 9; j++) {
                    int cc = 0;
                    #pragma unroll
                    for (int k = 0; k < 9; k++)
                        cc += (pv[k] == pv[j]) ? 1 : 0;
                    const bool a = (pv[j] != 0) & (cc == 2);
                    act |= a ? (1 << j) : 0;
                    tor |= a ? pv[j] : 0;
                }
                #pragma unroll
                for (int c = 0; c < 9; c++) {
                    int erase;
                    if ((act >> c) & 1) {
                        erase = 0;
                        #pragma unroll
                        for (int j = 0; j < 9; j++)
                            if (((act >> j) & 1) && pv[j] != pv[c])
                                erase |= pv[j];
                    } else {
                        erase = tor;
                    }
                    const int keep = m[c] & ~erase;
                    #pragma unroll
                    for (int d = 0; d < 9; d++)
                        go[d * 81 + c] = ((keep >> d) & 1) ? 1.0f : 0.0f;
                }
            }
        }
    }

    // drain: last store must finish reading smem before the CTA exits
    if (tid == 0)
        asm volatile("cp.async.bulk.wait_group.read 0;" ::: "memory");
}

extern "C" void kernel_launch(void* const* d_in, const int* in_sizes, int n_in,
                              void* d_out, int out_size)
{
    const float* mask = (const float*)d_in[0];
    float* out = (float*)d_out;
    const int nPuz = in_sizes[0] / PUZ;                 // 32768
    const int nTiles = (nPuz + PPB - 1) / PPB;          // 4096
    const int grid = (nTiles < GRID_CTAS) ? nTiles : GRID_CTAS;
    sudoku_doubles_kernel<<<grid, THREADS>>>(mask, out, nPuz, nTiles);
}